// round 8
// baseline (speedup 1.0000x reference)
#include <cuda_runtime.h>
#include <cuda_bf16.h>
#include <cstdint>

// Embedding gather: out[b, t, :] = weight[idxes[b, t], :]
// idxes: [8, 2048] int32, weight: [50257, 1024] f32, out: [8,2048,1024] f32
//
// R7: tile tuning at the LTS wall. Five structurally different kernels all
// land at 18.5-19us = 128MB compulsory traffic through the path-independent
// LTS cap (~6300 B/cyc). Reads are L2-hot (weight set resident across graph
// replays); writes stream to DRAM with __stcs (evict-first) to keep them
// from polluting L2. This round: 16 rows/CTA to amortize index loads and
// lengthen per-warp store bursts; otherwise identical to the R6 winner.

#define FEATURES 1024
#define VEC4_PER_ROW (FEATURES / 4)   // 256
#define ROWS_PER_CTA 16

__global__ __launch_bounds__(256) void embedding_gather_stcs16_kernel(
    const int* __restrict__ idxes,
    const float4* __restrict__ weight,
    float4* __restrict__ out,
    int n_rows)
{
    const int t = threadIdx.x;                     // 0..255 = column slot
    const int base = blockIdx.x * ROWS_PER_CTA;

    if (base + ROWS_PER_CTA <= n_rows) {
        // Vectorized broadcast index load: 4x int4.
        int idx[ROWS_PER_CTA];
        const int4* ip = (const int4*)(idxes + base);
#pragma unroll
        for (int g = 0; g < ROWS_PER_CTA / 4; g++) {
            int4 iv = __ldg(ip + g);
            idx[g * 4 + 0] = iv.x;
            idx[g * 4 + 1] = iv.y;
            idx[g * 4 + 2] = iv.z;
            idx[g * 4 + 3] = iv.w;
        }

        // Process in groups of 4 rows: load 4, stream-store 4. ptxas keeps
        // ~4 loads in flight; deeper batches get collapsed anyway (observed
        // regs=32 across R2/R3/R6), and we're LTS-bound, not latency-bound.
#pragma unroll
        for (int g = 0; g < ROWS_PER_CTA / 4; g++) {
            float4 v[4];
#pragma unroll
            for (int r = 0; r < 4; r++)
                v[r] = __ldg(weight + (size_t)idx[g * 4 + r] * VEC4_PER_ROW + t);
#pragma unroll
            for (int r = 0; r < 4; r++)
                __stcs(out + (size_t)(base + g * 4 + r) * VEC4_PER_ROW + t, v[r]);
        }
    } else {
        // Tail (unused at 16384 rows; kept for safety).
        for (int r = 0; r < ROWS_PER_CTA; r++) {
            int row = base + r;
            if (row >= n_rows) break;
            int src = idxes[row];
            __stcs(out + (size_t)row * VEC4_PER_ROW + t,
                   __ldg(weight + (size_t)src * VEC4_PER_ROW + t));
        }
    }
}

extern "C" void kernel_launch(void* const* d_in, const int* in_sizes, int n_in,
                              void* d_out, int out_size)
{
    const int*    idxes  = (const int*)d_in[0];
    const float4* weight = (const float4*)d_in[1];
    float4*       out    = (float4*)d_out;

    int n_rows = in_sizes[0];      // 8 * 2048 = 16384
    int n_ctas = (n_rows + ROWS_PER_CTA - 1) / ROWS_PER_CTA;

    embedding_gather_stcs16_kernel<<<n_ctas, 256>>>(idxes, weight, out, n_rows);
}

// round 9
// speedup vs baseline: 1.3681x; 1.3681x over previous
#include <cuda_runtime.h>
#include <cuda_bf16.h>
#include <cstdint>

// Embedding gather: out[b, t, :] = weight[idxes[b, t], :]
// idxes: [8, 2048] int32, weight: [50257, 1024] f32, out: [8,2048,1024] f32
//
// R9: grid-parallelism sweep at the throughput wall.
//   1 row/CTA (16384 CTAs, MLP1): 23.0us   [R1]
//   8 rows/CTA (2048 CTAs):       18.8us   [R6, best]
//  16 rows/CTA (1024 CTAs):       22.3us   [R7, occupancy-starved]
// This round: 4 rows/CTA (4096 CTAs, ~28/SM) — more concurrent CTAs to feed
// the LTS queues and smooth wave-tail, MLP=4 per thread (what ptxas grants
// at regs=32 anyway). __ldg reads (L2-resident weight set) + __stcs writes
// (evict-first, zero-reuse output stays out of L2).

#define FEATURES 1024
#define VEC4_PER_ROW (FEATURES / 4)   // 256
#define ROWS_PER_CTA 4

__global__ __launch_bounds__(256) void embedding_gather_stcs4_kernel(
    const int* __restrict__ idxes,
    const float4* __restrict__ weight,
    float4* __restrict__ out,
    int n_rows)
{
    const int t = threadIdx.x;                     // 0..255 = column slot
    const int base = blockIdx.x * ROWS_PER_CTA;

    if (base + ROWS_PER_CTA <= n_rows) {
        // One vectorized broadcast index load.
        int4 iv = __ldg((const int4*)(idxes + base));
        int idx[ROWS_PER_CTA] = {iv.x, iv.y, iv.z, iv.w};

        float4 v[ROWS_PER_CTA];
#pragma unroll
        for (int r = 0; r < ROWS_PER_CTA; r++)
            v[r] = __ldg(weight + (size_t)idx[r] * VEC4_PER_ROW + t);

#pragma unroll
        for (int r = 0; r < ROWS_PER_CTA; r++)
            __stcs(out + (size_t)(base + r) * VEC4_PER_ROW + t, v[r]);
    } else {
        // Tail (unused at 16384 rows; kept for safety).
        for (int r = 0; r < ROWS_PER_CTA; r++) {
            int row = base + r;
            if (row >= n_rows) break;
            int src = idxes[row];
            __stcs(out + (size_t)row * VEC4_PER_ROW + t,
                   __ldg(weight + (size_t)src * VEC4_PER_ROW + t));
        }
    }
}

extern "C" void kernel_launch(void* const* d_in, const int* in_sizes, int n_in,
                              void* d_out, int out_size)
{
    const int*    idxes  = (const int*)d_in[0];
    const float4* weight = (const float4*)d_in[1];
    float4*       out    = (float4*)d_out;

    int n_rows = in_sizes[0];      // 8 * 2048 = 16384
    int n_ctas = (n_rows + ROWS_PER_CTA - 1) / ROWS_PER_CTA;

    embedding_gather_stcs4_kernel<<<n_ctas, 256>>>(idxes, weight, out, n_rows);
}